// round 7
// baseline (speedup 1.0000x reference)
#include <cuda_runtime.h>
#include <cstdint>

#define B 128
#define T 1024
#define I 512
#define H 1024
#define O 512
#define NCTA 128

__device__ float g_xproj[(size_t)T * B * H];   // [t][b][h], 512 MB scratch
__device__ float g_h[2 * B * H];               // double-buffered h state
__device__ unsigned g_cnt;                     // grid barrier count (returns to 0)
__device__ unsigned g_gen;                     // grid barrier generation

__device__ __forceinline__ float rtf(float x) {
    unsigned u; asm("cvt.rna.tf32.f32 %0,%1;" : "=r"(u) : "f"(x));
    return __uint_as_float(u);
}
__device__ __forceinline__ unsigned f2u(float x) { return __float_as_uint(x); }

#define MMA(d, a0, a1, a2, a3, b0, b1) asm volatile( \
    "mma.sync.aligned.m16n8k8.row.col.f32.tf32.tf32.f32 " \
    "{%0,%1,%2,%3},{%4,%5,%6,%7},{%8,%9},{%0,%1,%2,%3};" \
    : "+f"(d[0]), "+f"(d[1]), "+f"(d[2]), "+f"(d[3]) \
    : "r"(a0), "r"(a1), "r"(a2), "r"(a3), "r"(b0), "r"(b1))

// ---------------- Phase 1: xproj[t][b][h] = x[b][t][:]·Wx[h][:] + b_ih ----------------
// CTA tile 64(M) x 256(N), BK=32. 8 warps as 2x4, each 32m x 64n.
__global__ __launch_bounds__(256) void xproj_k(const float* __restrict__ x,
                                               const float* __restrict__ Wih,
                                               const float* __restrict__ bih) {
    __shared__ float As[64 * 36];
    __shared__ float Bs[256 * 36];
    int tid = threadIdx.x, lane = tid & 31, wid = tid >> 5;
    int wm = wid >> 2, wn = wid & 3, lq = lane >> 2, lr = lane & 3;
    size_t r0 = (size_t)blockIdx.x * 64;
    int n0 = blockIdx.y * 256;

    float acc[2][8][4];
#pragma unroll
    for (int i = 0; i < 2; i++)
#pragma unroll
        for (int j = 0; j < 8; j++)
#pragma unroll
            for (int k = 0; k < 4; k++) acc[i][j][k] = 0.f;

    for (int k0 = 0; k0 < I; k0 += 32) {
        {   // stage A: x rows (64 x 32), tf32-rounded
            int row = tid >> 2, kk = (tid & 3) * 8;
            const float* s = x + (r0 + row) * I + k0 + kk;
            float* d = As + row * 36 + kk;
#pragma unroll
            for (int j = 0; j < 8; j += 4) {
                float4 v = *(const float4*)(s + j);
                d[j] = rtf(v.x); d[j + 1] = rtf(v.y); d[j + 2] = rtf(v.z); d[j + 3] = rtf(v.w);
            }
        }
        {   // stage B: Wx rows (256 x 32); Wx[n][k] = Wih[n*1536 + k]
            const float* s = Wih + (size_t)(n0 + tid) * (I + H) + k0;
            float* d = Bs + tid * 36;
#pragma unroll
            for (int j = 0; j < 32; j += 4) {
                float4 v = *(const float4*)(s + j);
                d[j] = rtf(v.x); d[j + 1] = rtf(v.y); d[j + 2] = rtf(v.z); d[j + 3] = rtf(v.w);
            }
        }
        __syncthreads();
#pragma unroll
        for (int ks = 0; ks < 4; ks++) {
            int ka = ks * 8;
            unsigned a[2][4];
#pragma unroll
            for (int mt = 0; mt < 2; mt++) {
                int ba = (wm * 32 + mt * 16 + lq) * 36 + ka + lr;
                a[mt][0] = f2u(As[ba]);           a[mt][1] = f2u(As[ba + 8 * 36]);
                a[mt][2] = f2u(As[ba + 4]);       a[mt][3] = f2u(As[ba + 8 * 36 + 4]);
            }
#pragma unroll
            for (int nt = 0; nt < 8; nt++) {
                int bb = (wn * 64 + nt * 8 + lq) * 36 + ka + lr;
                unsigned b0 = f2u(Bs[bb]), b1 = f2u(Bs[bb + 4]);
#pragma unroll
                for (int mt = 0; mt < 2; mt++)
                    MMA(acc[mt][nt], a[mt][0], a[mt][1], a[mt][2], a[mt][3], b0, b1);
            }
        }
        __syncthreads();
    }
    // epilogue: C row r = b*T + t  ->  g_xproj[(t*B + b)*H + h] + bias
#pragma unroll
    for (int mt = 0; mt < 2; mt++) {
        size_t gr = r0 + wm * 32 + mt * 16 + lq;
        int bb = (int)(gr >> 10), tt = (int)(gr & 1023);
#pragma unroll
        for (int nt = 0; nt < 8; nt++) {
            int gc = n0 + wn * 64 + nt * 8 + lr * 2;
            float bx = bih[gc], by = bih[gc + 1];
            float2 v0 = make_float2(acc[mt][nt][0] + bx, acc[mt][nt][1] + by);
            float2 v1 = make_float2(acc[mt][nt][2] + bx, acc[mt][nt][3] + by);
            *(float2*)(g_xproj + ((size_t)tt * B + bb) * H + gc) = v0;
            *(float2*)(g_xproj + ((size_t)(tt + 8) * B + bb) * H + gc) = v1;
        }
    }
}

// ---------------- Phase 2: persistent scan kernel ----------------
#define WH_S 1028                 // padded row stride (bank-conflict-free)
#define HS_S 260
#define HSBUF (32 * HS_S)
#define SCAN_SMEM ((32 * WH_S + 2 * HSBUF) * 4)   // 198144 B

__device__ __forceinline__ void gridsync() {
    __threadfence();
    __syncthreads();
    if (threadIdx.x == 0) {
        volatile unsigned* gen = &g_gen;
        unsigned g0 = *gen;
        if (atomicAdd(&g_cnt, 1u) == NCTA - 1) {
            g_cnt = 0;
            __threadfence();
            *gen = g0 + 1;
        } else {
            while (*gen == g0) { __nanosleep(32); }
        }
    }
    __syncthreads();
}

__global__ __launch_bounds__(256) void scan_k(const float* __restrict__ Wih) {
    extern __shared__ float sm[];
    float* Wh_s = sm;                 // [32][1028] tf32 Wh slice, persistent
    float* h_s = sm + 32 * WH_S;      // [2][32][260] h chunk double buffer
    int tid = threadIdx.x, lane = tid & 31, wid = tid >> 5;
    int wm = wid >> 2, wn = wid & 3, lq = lane >> 2, lr = lane & 3;
    int blk = blockIdx.x, b0 = (blk >> 5) * 32, n0 = (blk & 31) * 32;

    // zero h buffer 0, row = blk (disjoint per CTA)
    *(float4*)(g_h + blk * H + tid * 4) = make_float4(0.f, 0.f, 0.f, 0.f);

    // load Wh slice: Wh[n][k] = Wih[(n0+n)*1536 + 512 + k], tf32-rounded
    {
        int n = tid >> 3, kb = (tid & 7) * 128;
        const float* s = Wih + (size_t)(n0 + n) * (I + H) + I + kb;
        float* d = Wh_s + n * WH_S + kb;
#pragma unroll
        for (int j = 0; j < 128; j += 4) {
            float4 v = *(const float4*)(s + j);
            d[j] = rtf(v.x); d[j + 1] = rtf(v.y); d[j + 2] = rtf(v.z); d[j + 3] = rtf(v.w);
        }
    }
    gridsync();

    int row0 = wm * 16 + lq, coll = wn * 8 + lr * 2;
    int srow = tid >> 3, scol = (tid & 7) * 32;
    int ar0 = (wm * 16 + lq) * HS_S + lr, ar1 = ar0 + 8 * HS_S;
    int brb = (wn * 8 + lq) * WH_S + lr;

    for (int t = 0; t < T; t++) {
        int cur = t & 1, nxt = cur ^ 1;
        const float* xpp = g_xproj + ((size_t)t * B + b0 + row0) * H + n0 + coll;
        float2 xp0 = __ldcs((const float2*)xpp);
        float2 xp1 = __ldcs((const float2*)(xpp + 8 * H));
        float acc[4] = {0.f, 0.f, 0.f, 0.f};

        const float* hb = g_h + cur * (B * H) + (b0 + srow) * H + scol;
        float4 st[8];
#pragma unroll
        for (int j = 0; j < 8; j++) st[j] = __ldcg((const float4*)(hb + j * 4));
        {
            float* d = h_s + srow * HS_S + scol;
#pragma unroll
            for (int j = 0; j < 8; j++) *(float4*)(d + j * 4) = st[j];
        }
        __syncthreads();

        for (int kc = 0; kc < 4; kc++) {
            if (kc < 3) {   // prefetch next 256-k chunk (latency hidden by mma)
                const float* s2 = hb + (kc + 1) * 256;
#pragma unroll
                for (int j = 0; j < 8; j++) st[j] = __ldcg((const float4*)(s2 + j * 4));
            }
            const float* hs = h_s + (kc & 1) * HSBUF;
            const float* wk = Wh_s + kc * 256;
#pragma unroll
            for (int ks = 0; ks < 32; ks++) {
                int ka = ks * 8;
                unsigned a0 = f2u(hs[ar0 + ka]),     a1 = f2u(hs[ar1 + ka]);
                unsigned a2 = f2u(hs[ar0 + ka + 4]), a3 = f2u(hs[ar1 + ka + 4]);
                unsigned b0r = f2u(wk[brb + ka]),    b1r = f2u(wk[brb + ka + 4]);
                MMA(acc, a0, a1, a2, a3, b0r, b1r);
            }
            if (kc < 3) {   // store prefetched chunk into the free buffer
                float* d = h_s + ((kc + 1) & 1) * HSBUF + srow * HS_S + scol;
#pragma unroll
                for (int j = 0; j < 8; j++) *(float4*)(d + j * 4) = st[j];
            }
            __syncthreads();
        }

        float2 o0, o1;
        o0.x = rtf(tanhf(acc[0] + xp0.x)); o0.y = rtf(tanhf(acc[1] + xp0.y));
        o1.x = rtf(tanhf(acc[2] + xp1.x)); o1.y = rtf(tanhf(acc[3] + xp1.y));
        float* hw = g_h + nxt * (B * H) + (b0 + row0) * H + n0 + coll;
        *(float2*)hw = o0;
        *(float2*)(hw + 8 * H) = o1;
        gridsync();
    }
}

// ---------------- Phase 3: y = h_final · W_ho^T + b_ho (h_final in g_h[0]) ----------------
__global__ __launch_bounds__(256) void out_k(const float* __restrict__ Who,
                                             const float* __restrict__ bho,
                                             float* __restrict__ y) {
    int idx = blockIdx.x * 256 + threadIdx.x;   // idx = b*512 + o
    int o = idx & (O - 1), bb = idx >> 9;
    const float4* hv = (const float4*)(g_h + bb * H);
    const float4* wv = (const float4*)(Who + (size_t)o * H);
    float s = 0.f;
#pragma unroll 8
    for (int j = 0; j < H / 4; j++) {
        float4 a = hv[j], w = wv[j];
        s += a.x * w.x + a.y * w.y + a.z * w.z + a.w * w.w;
    }
    y[idx] = s + bho[o];
}

extern "C" void kernel_launch(void* const* d_in, const int* in_sizes, int n_in,
                              void* d_out, int out_size) {
    const float* x   = (const float*)d_in[0];
    const float* Wih = (const float*)d_in[1];
    const float* bih = (const float*)d_in[2];
    const float* Who = (const float*)d_in[3];
    const float* bho = (const float*)d_in[4];

    cudaFuncSetAttribute(scan_k, cudaFuncAttributeMaxDynamicSharedMemorySize, SCAN_SMEM);

    xproj_k<<<dim3((B * T) / 64, H / 256), 256>>>(x, Wih, bih);
    scan_k<<<NCTA, 256, SCAN_SMEM>>>(Wih);
    out_k<<<(B * O) / 256, 256>>>(Who, bho, (float*)d_out);
}

// round 8
// speedup vs baseline: 1.2644x; 1.2644x over previous
#include <cuda_runtime.h>
#include <cstdint>

#define B 128
#define T 1024
#define I 512
#define H 1024
#define O 512
#define NCTA 128
#define BH (B * H)

__device__ float g_xproj[(size_t)T * B * H];   // [t][b][h] scratch
__device__ float g_h[2 * BH];                  // double-buffered h state
__device__ unsigned g_flags[NCTA];             // per-CTA epoch flags (groups of 32 contiguous)

__device__ __forceinline__ float rtf(float x) {
    unsigned u; asm("cvt.rna.tf32.f32 %0,%1;" : "=r"(u) : "f"(x));
    return __uint_as_float(u);
}
__device__ __forceinline__ unsigned f2u(float x) { return __float_as_uint(x); }

__device__ __forceinline__ unsigned ld_acq(const unsigned* p) {
    unsigned v; asm volatile("ld.acquire.gpu.global.u32 %0,[%1];" : "=r"(v) : "l"(p)); return v;
}
__device__ __forceinline__ void st_rel(unsigned* p, unsigned v) {
    asm volatile("st.release.gpu.global.u32 [%0],%1;" :: "l"(p), "r"(v));
}

#define MMA(d, a0, a1, a2, a3, b0, b1) asm volatile( \
    "mma.sync.aligned.m16n8k8.row.col.f32.tf32.tf32.f32 " \
    "{%0,%1,%2,%3},{%4,%5,%6,%7},{%8,%9},{%0,%1,%2,%3};" \
    : "+f"(d[0]), "+f"(d[1]), "+f"(d[2]), "+f"(d[3]) \
    : "r"(a0), "r"(a1), "r"(a2), "r"(a3), "r"(b0), "r"(b1))

// ---------------- Phase 1: xproj[t][b][h] = x[b][t][:]·Wx[h][:] + b_ih ----------------
__global__ __launch_bounds__(256) void xproj_k(const float* __restrict__ x,
                                               const float* __restrict__ Wih,
                                               const float* __restrict__ bih) {
    __shared__ float As[64 * 36];
    __shared__ float Bs[256 * 36];
    int tid = threadIdx.x, lane = tid & 31, wid = tid >> 5;
    int wm = wid >> 2, wn = wid & 3, lq = lane >> 2, lr = lane & 3;
    size_t r0 = (size_t)blockIdx.x * 64;
    int n0 = blockIdx.y * 256;

    float acc[2][8][4];
#pragma unroll
    for (int i = 0; i < 2; i++)
#pragma unroll
        for (int j = 0; j < 8; j++)
#pragma unroll
            for (int k = 0; k < 4; k++) acc[i][j][k] = 0.f;

    for (int k0 = 0; k0 < I; k0 += 32) {
        {
            int row = tid >> 2, kk = (tid & 3) * 8;
            const float* s = x + (r0 + row) * I + k0 + kk;
            float* d = As + row * 36 + kk;
#pragma unroll
            for (int j = 0; j < 8; j += 4) {
                float4 v = *(const float4*)(s + j);
                d[j] = rtf(v.x); d[j + 1] = rtf(v.y); d[j + 2] = rtf(v.z); d[j + 3] = rtf(v.w);
            }
        }
        {
            const float* s = Wih + (size_t)(n0 + tid) * (I + H) + k0;
            float* d = Bs + tid * 36;
#pragma unroll
            for (int j = 0; j < 32; j += 4) {
                float4 v = *(const float4*)(s + j);
                d[j] = rtf(v.x); d[j + 1] = rtf(v.y); d[j + 2] = rtf(v.z); d[j + 3] = rtf(v.w);
            }
        }
        __syncthreads();
#pragma unroll
        for (int ks = 0; ks < 4; ks++) {
            int ka = ks * 8;
            unsigned a[2][4];
#pragma unroll
            for (int mt = 0; mt < 2; mt++) {
                int ba = (wm * 32 + mt * 16 + lq) * 36 + ka + lr;
                a[mt][0] = f2u(As[ba]);     a[mt][1] = f2u(As[ba + 8 * 36]);
                a[mt][2] = f2u(As[ba + 4]); a[mt][3] = f2u(As[ba + 8 * 36 + 4]);
            }
#pragma unroll
            for (int nt = 0; nt < 8; nt++) {
                int bb = (wn * 64 + nt * 8 + lq) * 36 + ka + lr;
                unsigned b0 = f2u(Bs[bb]), b1 = f2u(Bs[bb + 4]);
#pragma unroll
                for (int mt = 0; mt < 2; mt++)
                    MMA(acc[mt][nt], a[mt][0], a[mt][1], a[mt][2], a[mt][3], b0, b1);
            }
        }
        __syncthreads();
    }
#pragma unroll
    for (int mt = 0; mt < 2; mt++) {
        size_t gr = r0 + wm * 32 + mt * 16 + lq;
        int bb = (int)(gr >> 10), tt = (int)(gr & 1023);
#pragma unroll
        for (int nt = 0; nt < 8; nt++) {
            int gc = n0 + wn * 64 + nt * 8 + lr * 2;
            float bx = bih[gc], by = bih[gc + 1];
            float2 v0 = make_float2(acc[mt][nt][0] + bx, acc[mt][nt][1] + by);
            float2 v1 = make_float2(acc[mt][nt][2] + bx, acc[mt][nt][3] + by);
            *(float2*)(g_xproj + ((size_t)tt * B + bb) * H + gc) = v0;
            *(float2*)(g_xproj + ((size_t)(tt + 8) * B + bb) * H + gc) = v1;
        }
    }
}

// ---------------- Phase 2: persistent scan, v2 ----------------
// 128 CTAs = 4 b-groups x 32 n-blocks. 512 threads = 16 warps = 2 n-halves x 8 k-slices.
// Wh fragments register-resident; h staged to smem once per step; per-group flag sync.
#define HS_STRIDE 1028                         // 1028 % 32 == 4 -> A-frag LDS conflict-free
#define P_STRIDE 33
#define SCAN_SMEM ((32 * HS_STRIDE + 8 * 32 * P_STRIDE) * 4)   // 165376 B

__global__ __launch_bounds__(512) void scan_k(const float* __restrict__ Wih) {
    extern __shared__ float sm[];
    float* h_s  = sm;                          // [32][1028] staged h block
    float* part = sm + 32 * HS_STRIDE;         // [8][32][33] k-split partials

    int tid = threadIdx.x, lane = tid & 31, wid = tid >> 5;
    int lq = lane >> 2, lr = lane & 3;
    int nh = wid & 1, kq = wid >> 1;           // n-half (16), k-slice (128)
    int blk = blockIdx.x;
    int b0 = (blk >> 5) * 32, n0 = (blk & 31) * 32;
    unsigned* gflag = g_flags + (blk & ~31);   // this CTA's 32-flag group

    unsigned base = ld_acq(&g_flags[blk]);     // uniform at every kernel boundary

    // zero h buffer 0, row = blk
    *(float2*)(g_h + blk * H + tid * 2) = make_float2(0.f, 0.f);

    // load Wh fragments into registers (constant across all steps)
    float Br[2][16][2];
#pragma unroll
    for (int nt = 0; nt < 2; nt++) {
        const float* wp = Wih + (size_t)(n0 + nh * 16 + nt * 8 + lq) * (I + H) + I + kq * 128 + lr;
#pragma unroll
        for (int ks = 0; ks < 16; ks++) {
            Br[nt][ks][0] = rtf(__ldg(wp + ks * 8));
            Br[nt][ks][1] = rtf(__ldg(wp + ks * 8 + 4));
        }
    }

    __syncthreads();
    if (tid == 0) st_rel(&g_flags[blk], base + 1);   // publish zeroed h

    // staging / reduce thread mappings
    int srow = tid >> 4, scol = (tid & 15) * 4;       // stage: row, scattered float4s
    int rm = tid >> 4, rn = (tid & 15) * 2;           // reduce: 2 outputs per thread

    for (int t = 0; t < T; t++) {
        int cur = t & 1, nxt = cur ^ 1;
        unsigned tgt = base + 1 + (unsigned)t;

        // prefetch xproj for this thread's two outputs
        float2 xp = __ldcs((const float2*)(g_xproj + ((size_t)t * B + b0 + rm) * H + n0 + rn));

        // wait: all 32 group producers published h for this step
        {
            unsigned v;
            do { v = ld_acq(gflag + lane); } while (__any_sync(0xffffffffu, (int)(v - tgt) < 0));
        }

        // stage h block [32 x 1024] -> smem (L2-coherent loads)
        {
            const float* hg = g_h + cur * BH + (b0 + srow) * H + scol;
            float* hd = h_s + srow * HS_STRIDE + scol;
#pragma unroll
            for (int j = 0; j < 16; j++)
                *(float4*)(hd + j * 64) = __ldcg((const float4*)(hg + j * 64));
        }
        __syncthreads();

        // mma: this warp covers m32 x n16(nh) x k128(kq)
        float acc[2][2][4];
#pragma unroll
        for (int mt = 0; mt < 2; mt++)
#pragma unroll
            for (int nt = 0; nt < 2; nt++)
#pragma unroll
                for (int c = 0; c < 4; c++) acc[mt][nt][c] = 0.f;

        int kbase = kq * 128;
#pragma unroll
        for (int ks = 0; ks < 16; ks++) {
            int ka = kbase + ks * 8;
#pragma unroll
            for (int mt = 0; mt < 2; mt++) {
                const float* ap = h_s + (mt * 16 + lq) * HS_STRIDE + ka + lr;
                unsigned a0 = f2u(ap[0]), a1 = f2u(ap[8 * HS_STRIDE]);
                unsigned a2 = f2u(ap[4]), a3 = f2u(ap[8 * HS_STRIDE + 4]);
#pragma unroll
                for (int nt = 0; nt < 2; nt++)
                    MMA(acc[mt][nt], a0, a1, a2, a3,
                        f2u(Br[nt][ks][0]), f2u(Br[nt][ks][1]));
            }
        }

        // write k-split partials
        {
            float* pp = part + kq * (32 * P_STRIDE);
#pragma unroll
            for (int mt = 0; mt < 2; mt++)
#pragma unroll
                for (int nt = 0; nt < 2; nt++) {
                    int m = mt * 16 + lq, n = nh * 16 + nt * 8 + lr * 2;
                    pp[m * P_STRIDE + n]           = acc[mt][nt][0];
                    pp[m * P_STRIDE + n + 1]       = acc[mt][nt][1];
                    pp[(m + 8) * P_STRIDE + n]     = acc[mt][nt][2];
                    pp[(m + 8) * P_STRIDE + n + 1] = acc[mt][nt][3];
                }
        }
        __syncthreads();

        // reduce 8 partials + xproj, tanh, store h_out
        {
            float s0 = xp.x, s1 = xp.y;
#pragma unroll
            for (int k = 0; k < 8; k++) {
                const float* pp = part + k * (32 * P_STRIDE) + rm * P_STRIDE + rn;
                s0 += pp[0]; s1 += pp[1];
            }
            float o0 = rtf(tanhf(s0)), o1 = rtf(tanhf(s1));
            float* hw = g_h + nxt * BH + (b0 + rm) * H + n0 + rn;
            float2 ov = make_float2(o0, o1);
            __stcg((float2*)hw, ov);
        }

        __syncthreads();
        if (tid == 0) st_rel(&g_flags[blk], tgt + 1);  // publish step output
    }
}

// ---------------- Phase 3: y = h_final · W_ho^T + b_ho (h_final in g_h[0..BH)) ----------------
__global__ __launch_bounds__(256) void out_k(const float* __restrict__ Who,
                                             const float* __restrict__ bho,
                                             float* __restrict__ y) {
    int idx = blockIdx.x * 256 + threadIdx.x;   // idx = b*512 + o
    int o = idx & (O - 1), bb = idx >> 9;
    const float4* hv = (const float4*)(g_h + bb * H);
    const float4* wv = (const float4*)(Who + (size_t)o * H);
    float s = 0.f;
#pragma unroll 8
    for (int j = 0; j < H / 4; j++) {
        float4 a = hv[j], w = wv[j];
        s += a.x * w.x + a.y * w.y + a.z * w.z + a.w * w.w;
    }
    y[idx] = s + bho[o];
}

extern "C" void kernel_launch(void* const* d_in, const int* in_sizes, int n_in,
                              void* d_out, int out_size) {
    const float* x   = (const float*)d_in[0];
    const float* Wih = (const float*)d_in[1];
    const float* bih = (const float*)d_in[2];
    const float* Who = (const float*)d_in[3];
    const float* bho = (const float*)d_in[4];

    cudaFuncSetAttribute(scan_k, cudaFuncAttributeMaxDynamicSharedMemorySize, SCAN_SMEM);

    xproj_k<<<dim3((B * T) / 64, H / 256), 256>>>(x, Wih, bih);
    scan_k<<<NCTA, 512, SCAN_SMEM>>>(Wih);
    out_k<<<(B * O) / 256, 256>>>(Who, bho, (float*)d_out);
}

// round 10
// speedup vs baseline: 1.4310x; 1.1317x over previous
#include <cuda_runtime.h>
#include <cstdint>

#define B 128
#define T 1024
#define I 512
#define H 1024
#define O 512
#define NCTA 128
#define BH (B * H)

__device__ float g_xproj[(size_t)T * B * H];   // [t][b][h] scratch
__device__ float g_h[2 * BH];                  // double-buffered h state
__device__ unsigned g_flags[NCTA];             // per-CTA epoch flags

__device__ __forceinline__ float rtf(float x) {
    unsigned u; asm("cvt.rna.tf32.f32 %0,%1;" : "=r"(u) : "f"(x));
    return __uint_as_float(u);
}
__device__ __forceinline__ unsigned f2u(float x) { return __float_as_uint(x); }

__device__ __forceinline__ unsigned ld_acq(const unsigned* p) {
    unsigned v; asm volatile("ld.acquire.gpu.global.u32 %0,[%1];" : "=r"(v) : "l"(p)); return v;
}
__device__ __forceinline__ void st_rel(unsigned* p, unsigned v) {
    asm volatile("st.release.gpu.global.u32 [%0],%1;" :: "l"(p), "r"(v));
}

// fast tanh: tanh(x) = (e-1)/(e+1), e = 2^(2x*log2e) via MUFU ex2;
// reciprocal via magic init + 3 Newton iters (FMA pipe). |err| ~ 1e-6.
__device__ __forceinline__ float ftanh(float x) {
    float t = fminf(fmaxf(x * 2.8853900817779268f, -30.f), 30.f);
    float e; asm("ex2.approx.ftz.f32 %0,%1;" : "=f"(e) : "f"(t));
    float b = e + 1.f;
    float r = __uint_as_float(0x7EF311C3u - __float_as_uint(b));
    r = r * (2.f - b * r);
    r = r * (2.f - b * r);
    r = r * (2.f - b * r);
    return (e - 1.f) * r;
}

__device__ __forceinline__ void addx2(float2& a, float2 b) {
    unsigned long long ua = *(unsigned long long*)&a;
    unsigned long long ub = *(unsigned long long*)&b;
    asm("add.rn.f32x2 %0, %0, %1;" : "+l"(ua) : "l"(ub));
    a = *(float2*)&ua;
}

#define MMA(d, a0, a1, a2, a3, b0, b1) asm volatile( \
    "mma.sync.aligned.m16n8k8.row.col.f32.tf32.tf32.f32 " \
    "{%0,%1,%2,%3},{%4,%5,%6,%7},{%8,%9},{%0,%1,%2,%3};" \
    : "+f"(d[0]), "+f"(d[1]), "+f"(d[2]), "+f"(d[3]) \
    : "r"(a0), "r"(a1), "r"(a2), "r"(a3), "r"(b0), "r"(b1))

// ---------------- Phase 1: xproj[t][b][h] = x[b][t][:]·Wx[h][:] + b_ih ----------------
__global__ __launch_bounds__(256) void xproj_k(const float* __restrict__ x,
                                               const float* __restrict__ Wih,
                                               const float* __restrict__ bih) {
    __shared__ float As[64 * 36];
    __shared__ float Bs[256 * 36];
    int tid = threadIdx.x, lane = tid & 31, wid = tid >> 5;
    int wm = wid >> 2, wn = wid & 3, lq = lane >> 2, lr = lane & 3;
    size_t r0 = (size_t)blockIdx.x * 64;
    int n0 = blockIdx.y * 256;

    float acc[2][8][4];
#pragma unroll
    for (int i = 0; i < 2; i++)
#pragma unroll
        for (int j = 0; j < 8; j++)
#pragma unroll
            for (int k = 0; k < 4; k++) acc[i][j][k] = 0.f;

    for (int k0 = 0; k0 < I; k0 += 32) {
        {
            int row = tid >> 2, kk = (tid & 3) * 8;
            const float* s = x + (r0 + row) * I + k0 + kk;
            float* d = As + row * 36 + kk;
#pragma unroll
            for (int j = 0; j < 8; j += 4) {
                float4 v = *(const float4*)(s + j);
                d[j] = rtf(v.x); d[j + 1] = rtf(v.y); d[j + 2] = rtf(v.z); d[j + 3] = rtf(v.w);
            }
        }
        {
            const float* s = Wih + (size_t)(n0 + tid) * (I + H) + k0;
            float* d = Bs + tid * 36;
#pragma unroll
            for (int j = 0; j < 32; j += 4) {
                float4 v = *(const float4*)(s + j);
                d[j] = rtf(v.x); d[j + 1] = rtf(v.y); d[j + 2] = rtf(v.z); d[j + 3] = rtf(v.w);
            }
        }
        __syncthreads();
#pragma unroll
        for (int ks = 0; ks < 4; ks++) {
            int ka = ks * 8;
            unsigned a[2][4];
#pragma unroll
            for (int mt = 0; mt < 2; mt++) {
                int ba = (wm * 32 + mt * 16 + lq) * 36 + ka + lr;
                a[mt][0] = f2u(As[ba]);     a[mt][1] = f2u(As[ba + 8 * 36]);
                a[mt][2] = f2u(As[ba + 4]); a[mt][3] = f2u(As[ba + 8 * 36 + 4]);
            }
#pragma unroll
            for (int nt = 0; nt < 8; nt++) {
                int bb = (wn * 64 + nt * 8 + lq) * 36 + ka + lr;
                unsigned b0 = f2u(Bs[bb]), b1 = f2u(Bs[bb + 4]);
#pragma unroll
                for (int mt = 0; mt < 2; mt++)
                    MMA(acc[mt][nt], a[mt][0], a[mt][1], a[mt][2], a[mt][3], b0, b1);
            }
        }
        __syncthreads();
    }
#pragma unroll
    for (int mt = 0; mt < 2; mt++) {
        size_t gr = r0 + wm * 32 + mt * 16 + lq;
        int bb = (int)(gr >> 10), tt = (int)(gr & 1023);
#pragma unroll
        for (int nt = 0; nt < 8; nt++) {
            int gc = n0 + wn * 64 + nt * 8 + lr * 2;
            float bx = bih[gc], by = bih[gc + 1];
            float2 v0 = make_float2(acc[mt][nt][0] + bx, acc[mt][nt][1] + by);
            float2 v1 = make_float2(acc[mt][nt][2] + bx, acc[mt][nt][3] + by);
            *(float2*)(g_xproj + ((size_t)tt * B + bb) * H + gc) = v0;
            *(float2*)(g_xproj + ((size_t)(tt + 8) * B + bb) * H + gc) = v1;
        }
    }
}

// ---------------- Phase 2: persistent scan, v3 ----------------
// 128 CTAs = 4 b-groups x 32 n-blocks. 512 threads = 16 warps = 2 n-halves x 8 k-slices.
// Wh frags in regs; no-libdevice tanh; packed-f32x2 reduce; half-k stage/mma overlap.
#define HS_STRIDE 1028
#define P_STRIDE 36
#define SCAN_SMEM ((32 * HS_STRIDE + 8 * 32 * P_STRIDE) * 4)   // 168448 B

__global__ __launch_bounds__(512) void scan_k(const float* __restrict__ Wih) {
    extern __shared__ float sm[];
    float* h_s  = sm;                          // [32][1028] staged h block
    float* part = sm + 32 * HS_STRIDE;         // [8][32][36] k-split partials

    int tid = threadIdx.x, lane = tid & 31, wid = tid >> 5;
    int lq = lane >> 2, lr = lane & 3;
    int nh = wid & 1, kq = wid >> 1;           // n-half (16), k-slice (128)
    int blk = blockIdx.x;
    int b0 = (blk >> 5) * 32, n0 = (blk & 31) * 32;
    unsigned* gflag = g_flags + (blk & ~31);

    unsigned base = ld_acq(&g_flags[blk]);

    // zero h buffer 0, row = blk
    *(float2*)(g_h + blk * H + tid * 2) = make_float2(0.f, 0.f);

    // Wh fragments -> registers (constant across all steps)
    float Br[2][16][2];
#pragma unroll
    for (int nt = 0; nt < 2; nt++) {
        const float* wp = Wih + (size_t)(n0 + nh * 16 + nt * 8 + lq) * (I + H) + I + kq * 128 + lr;
#pragma unroll
        for (int ks = 0; ks < 16; ks++) {
            Br[nt][ks][0] = rtf(__ldg(wp + ks * 8));
            Br[nt][ks][1] = rtf(__ldg(wp + ks * 8 + 4));
        }
    }

    __syncthreads();
    if (tid == 0) st_rel(&g_flags[blk], base + 1);

    // thread maps
    int srow = tid >> 4, scol = (tid & 15) * 4;     // half0 stage: 512 thr, cols 0..511
    int tid2 = tid - 256;                            // half1 stage: warps 8-15
    int srow2 = tid2 >> 3, scol2 = (tid2 & 7) * 4;   // cols 512..1023
    int rm = tid >> 4, rn = (tid & 15) * 2;          // reduce: 2 outputs/thread
    int ar0 = (lq) * HS_STRIDE + lr;                 // A-frag bases (plus mt*16 rows)
    int kbase = kq * 128;

    for (int t = 0; t < T; t++) {
        int cur = t & 1, nxt = cur ^ 1;
        unsigned tgt = base + 1 + (unsigned)t;

        float2 xp = __ldcs((const float2*)(g_xproj + ((size_t)t * B + b0 + rm) * H + n0 + rn));

        // wait for all 32 group producers
        {
            unsigned v;
            do { v = ld_acq(gflag + lane); } while (__any_sync(0xffffffffu, (int)(v - tgt) < 0));
        }

        // stage half0 (cols 0..511), all threads
        {
            const float* hg = g_h + cur * BH + (b0 + srow) * H + scol;
            float* hd = h_s + srow * HS_STRIDE + scol;
#pragma unroll
            for (int j = 0; j < 8; j++)
                *(float4*)(hd + j * 64) = __ldcg((const float4*)(hg + j * 64));
        }
        __syncthreads();

        float acc[2][2][4];
#pragma unroll
        for (int mt = 0; mt < 2; mt++)
#pragma unroll
            for (int nt = 0; nt < 2; nt++)
#pragma unroll
                for (int c = 0; c < 4; c++) acc[mt][nt][c] = 0.f;

        if (kq < 4) {
            // mma over k-slice in half0
#pragma unroll
            for (int ks = 0; ks < 16; ks++) {
                int ka = kbase + ks * 8;
#pragma unroll
                for (int mt = 0; mt < 2; mt++) {
                    const float* ap = h_s + mt * 16 * HS_STRIDE + ar0 + ka;
                    unsigned a0 = f2u(ap[0]), a1 = f2u(ap[8 * HS_STRIDE]);
                    unsigned a2 = f2u(ap[4]), a3 = f2u(ap[8 * HS_STRIDE + 4]);
#pragma unroll
                    for (int nt = 0; nt < 2; nt++)
                        MMA(acc[mt][nt], a0, a1, a2, a3,
                            f2u(Br[nt][ks][0]), f2u(Br[nt][ks][1]));
                }
            }
        } else {
            // stage half1 (cols 512..1023), warps 8-15
            const float* hg2 = g_h + cur * BH + (b0 + srow2) * H + 512 + scol2;
            float* hd2 = h_s + srow2 * HS_STRIDE + 512 + scol2;
#pragma unroll
            for (int j = 0; j < 16; j++)
                *(float4*)(hd2 + j * 32) = __ldcg((const float4*)(hg2 + j * 32));
        }
        __syncthreads();

        if (kq >= 4) {
#pragma unroll
            for (int ks = 0; ks < 16; ks++) {
                int ka = kbase + ks * 8;
#pragma unroll
                for (int mt = 0; mt < 2; mt++) {
                    const float* ap = h_s + mt * 16 * HS_STRIDE + ar0 + ka;
                    unsigned a0 = f2u(ap[0]), a1 = f2u(ap[8 * HS_STRIDE]);
                    unsigned a2 = f2u(ap[4]), a3 = f2u(ap[8 * HS_STRIDE + 4]);
#pragma unroll
                    for (int nt = 0; nt < 2; nt++)
                        MMA(acc[mt][nt], a0, a1, a2, a3,
                            f2u(Br[nt][ks][0]), f2u(Br[nt][ks][1]));
                }
            }
        }
        // write k-split partials (all warps; disjoint kq regions)
        {
            float* pp = part + kq * (32 * P_STRIDE);
#pragma unroll
            for (int mt = 0; mt < 2; mt++)
#pragma unroll
                for (int nt = 0; nt < 2; nt++) {
                    int m = mt * 16 + lq, n = nh * 16 + nt * 8 + lr * 2;
                    pp[m * P_STRIDE + n]           = acc[mt][nt][0];
                    pp[m * P_STRIDE + n + 1]       = acc[mt][nt][1];
                    pp[(m + 8) * P_STRIDE + n]     = acc[mt][nt][2];
                    pp[(m + 8) * P_STRIDE + n + 1] = acc[mt][nt][3];
                }
        }
        __syncthreads();

        // packed reduce + fast tanh + store
        {
            float2 s = xp;
            const float* pb = part + rm * P_STRIDE + rn;
#pragma unroll
            for (int k = 0; k < 8; k++)
                addx2(s, *(const float2*)(pb + k * (32 * P_STRIDE)));
            float2 ov = make_float2(rtf(ftanh(s.x)), rtf(ftanh(s.y)));
            __stcg((float2*)(g_h + nxt * BH + (b0 + rm) * H + n0 + rn), ov);
        }

        __syncthreads();
        if (tid == 0) st_rel(&g_flags[blk], tgt + 1);
    }
}

// ---------------- Phase 3: y = h_final · W_ho^T + b_ho ----------------
__global__ __launch_bounds__(256) void out_k(const float* __restrict__ Who,
                                             const float* __restrict__ bho,
                                             float* __restrict__ y) {
    int idx = blockIdx.x * 256 + threadIdx.x;   // idx = b*512 + o
    int o = idx & (O - 1), bb = idx >> 9;
    const float4* hv = (const float4*)(g_h + bb * H);
    const float4* wv = (const float4*)(Who + (size_t)o * H);
    float s = 0.f;
#pragma unroll 8
    for (int j = 0; j < H / 4; j++) {
        float4 a = hv[j], w = wv[j];
        s += a.x * w.x + a.y * w.y + a.z * w.z + a.w * w.w;
    }
    y[idx] = s + bho[o];
}

extern "C" void kernel_launch(void* const* d_in, const int* in_sizes, int n_in,
                              void* d_out, int out_size) {
    const float* x   = (const float*)d_in[0];
    const float* Wih = (const float*)d_in[1];
    const float* bih = (const float*)d_in[2];
    const float* Who = (const float*)d_in[3];
    const float* bho = (const float*)d_in[4];

    cudaFuncSetAttribute(scan_k, cudaFuncAttributeMaxDynamicSharedMemorySize, SCAN_SMEM);

    xproj_k<<<dim3((B * T) / 64, H / 256), 256>>>(x, Wih, bih);
    scan_k<<<NCTA, 512, SCAN_SMEM>>>(Wih);
    out_k<<<(B * O) / 256, 256>>>(Who, bho, (float*)d_out);
}

// round 11
// speedup vs baseline: 2.5258x; 1.7650x over previous
#include <cuda_runtime.h>
#include <cstdint>

#define B 128
#define T 1024
#define I 512
#define H 1024
#define O 512
#define NCTA 128
#define BH (B * H)

__device__ float g_xproj[(size_t)T * B * H];   // [t][b][h] scratch
__device__ float g_h[2 * BH];                  // double-buffered h state
__device__ unsigned g_flags[NCTA];             // per-CTA epoch flags

__device__ __forceinline__ float rtf(float x) {
    unsigned u; asm("cvt.rna.tf32.f32 %0,%1;" : "=r"(u) : "f"(x));
    return __uint_as_float(u);
}
__device__ __forceinline__ unsigned f2u(float x) { return __float_as_uint(x); }

__device__ __forceinline__ unsigned ld_acq(const unsigned* p) {
    unsigned v; asm volatile("ld.acquire.gpu.global.u32 %0,[%1];" : "=r"(v) : "l"(p)); return v;
}
__device__ __forceinline__ void st_rel(unsigned* p, unsigned v) {
    asm volatile("st.release.gpu.global.u32 [%0],%1;" :: "l"(p), "r"(v));
}

// fast tanh: tanh(x) = (e-1)/(e+1), e = 2^(2x*log2e) via MUFU ex2;
// reciprocal via magic init + 3 Newton iters (FMA pipe). |err| ~ 1e-6.
__device__ __forceinline__ float ftanh(float x) {
    float t = fminf(fmaxf(x * 2.8853900817779268f, -30.f), 30.f);
    float e; asm("ex2.approx.ftz.f32 %0,%1;" : "=f"(e) : "f"(t));
    float b = e + 1.f;
    float r = __uint_as_float(0x7EF311C3u - __float_as_uint(b));
    r = r * (2.f - b * r);
    r = r * (2.f - b * r);
    r = r * (2.f - b * r);
    return (e - 1.f) * r;
}

__device__ __forceinline__ void addx2(float2& a, float2 b) {
    unsigned long long ua = *(unsigned long long*)&a;
    unsigned long long ub = *(unsigned long long*)&b;
    asm("add.rn.f32x2 %0, %0, %1;" : "+l"(ua) : "l"(ub));
    a = *(float2*)&ua;
}

#define MMA(d, a0, a1, a2, a3, b0, b1) asm volatile( \
    "mma.sync.aligned.m16n8k8.row.col.f32.tf32.tf32.f32 " \
    "{%0,%1,%2,%3},{%4,%5,%6,%7},{%8,%9},{%0,%1,%2,%3};" \
    : "+f"(d[0]), "+f"(d[1]), "+f"(d[2]), "+f"(d[3]) \
    : "r"(a0), "r"(a1), "r"(a2), "r"(a3), "r"(b0), "r"(b1))

// ---------------- Phase 1: xproj[t][b][h] = x[b][t][:]·Wx[h][:] + b_ih ----------------
__global__ __launch_bounds__(256) void xproj_k(const float* __restrict__ x,
                                               const float* __restrict__ Wih,
                                               const float* __restrict__ bih) {
    __shared__ float As[64 * 36];
    __shared__ float Bs[256 * 36];
    int tid = threadIdx.x, lane = tid & 31, wid = tid >> 5;
    int wm = wid >> 2, wn = wid & 3, lq = lane >> 2, lr = lane & 3;
    size_t r0 = (size_t)blockIdx.x * 64;
    int n0 = blockIdx.y * 256;

    float acc[2][8][4];
#pragma unroll
    for (int i = 0; i < 2; i++)
#pragma unroll
        for (int j = 0; j < 8; j++)
#pragma unroll
            for (int k = 0; k < 4; k++) acc[i][j][k] = 0.f;

    for (int k0 = 0; k0 < I; k0 += 32) {
        {
            int row = tid >> 2, kk = (tid & 3) * 8;
            const float* s = x + (r0 + row) * I + k0 + kk;
            float* d = As + row * 36 + kk;
#pragma unroll
            for (int j = 0; j < 8; j += 4) {
                float4 v = *(const float4*)(s + j);
                d[j] = rtf(v.x); d[j + 1] = rtf(v.y); d[j + 2] = rtf(v.z); d[j + 3] = rtf(v.w);
            }
        }
        {
            const float* s = Wih + (size_t)(n0 + tid) * (I + H) + k0;
            float* d = Bs + tid * 36;
#pragma unroll
            for (int j = 0; j < 32; j += 4) {
                float4 v = *(const float4*)(s + j);
                d[j] = rtf(v.x); d[j + 1] = rtf(v.y); d[j + 2] = rtf(v.z); d[j + 3] = rtf(v.w);
            }
        }
        __syncthreads();
#pragma unroll
        for (int ks = 0; ks < 4; ks++) {
            int ka = ks * 8;
            unsigned a[2][4];
#pragma unroll
            for (int mt = 0; mt < 2; mt++) {
                int ba = (wm * 32 + mt * 16 + lq) * 36 + ka + lr;
                a[mt][0] = f2u(As[ba]);     a[mt][1] = f2u(As[ba + 8 * 36]);
                a[mt][2] = f2u(As[ba + 4]); a[mt][3] = f2u(As[ba + 8 * 36 + 4]);
            }
#pragma unroll
            for (int nt = 0; nt < 8; nt++) {
                int bb = (wn * 64 + nt * 8 + lq) * 36 + ka + lr;
                unsigned b0 = f2u(Bs[bb]), b1 = f2u(Bs[bb + 4]);
#pragma unroll
                for (int mt = 0; mt < 2; mt++)
                    MMA(acc[mt][nt], a[mt][0], a[mt][1], a[mt][2], a[mt][3], b0, b1);
            }
        }
        __syncthreads();
    }
#pragma unroll
    for (int mt = 0; mt < 2; mt++) {
        size_t gr = r0 + wm * 32 + mt * 16 + lq;
        int bb = (int)(gr >> 10), tt = (int)(gr & 1023);
#pragma unroll
        for (int nt = 0; nt < 8; nt++) {
            int gc = n0 + wn * 64 + nt * 8 + lr * 2;
            float bx = bih[gc], by = bih[gc + 1];
            float2 v0 = make_float2(acc[mt][nt][0] + bx, acc[mt][nt][1] + by);
            float2 v1 = make_float2(acc[mt][nt][2] + bx, acc[mt][nt][3] + by);
            *(float2*)(g_xproj + ((size_t)tt * B + bb) * H + gc) = v0;
            *(float2*)(g_xproj + ((size_t)(tt + 8) * B + bb) * H + gc) = v1;
        }
    }
}

// ---------------- Phase 2: persistent scan, v4 ----------------
// 128 CTAs = 4 b-groups x 32 n-blocks. 512 threads = 16 warps = 2 n-halves x 8 k-slices.
// v4: delegated polling (1 warp per half; others sleep at BAR) + per-half flag
// pipelining (half1 poll/stage overlaps half0 mma behind named barrier).
#define HS_STRIDE 1028
#define P_STRIDE 36
#define SCAN_SMEM ((32 * HS_STRIDE + 8 * 32 * P_STRIDE) * 4)   // 168448 B

__global__ __launch_bounds__(512) void scan_k(const float* __restrict__ Wih) {
    extern __shared__ float sm[];
    float* h_s  = sm;                          // [32][1028] staged h block
    float* part = sm + 32 * HS_STRIDE;         // [8][32][36] k-split partials

    int tid = threadIdx.x, lane = tid & 31, wid = tid >> 5;
    int lq = lane >> 2, lr = lane & 3;
    int nh = wid & 1, kq = wid >> 1;           // n-half (16), k-slice (128)
    int blk = blockIdx.x;
    int b0 = (blk >> 5) * 32, n0 = (blk & 31) * 32;
    unsigned* gflag = g_flags + (blk & ~31);

    unsigned base = ld_acq(&g_flags[blk]);

    // zero h buffer 0, row = blk
    *(float2*)(g_h + blk * H + tid * 2) = make_float2(0.f, 0.f);

    // Wh fragments -> registers (constant across all steps)
    float Br[2][16][2];
#pragma unroll
    for (int nt = 0; nt < 2; nt++) {
        const float* wp = Wih + (size_t)(n0 + nh * 16 + nt * 8 + lq) * (I + H) + I + kq * 128 + lr;
#pragma unroll
        for (int ks = 0; ks < 16; ks++) {
            Br[nt][ks][0] = rtf(__ldg(wp + ks * 8));
            Br[nt][ks][1] = rtf(__ldg(wp + ks * 8 + 4));
        }
    }

    __syncthreads();
    if (tid == 0) st_rel(&g_flags[blk], base + 1);

    // thread maps
    int srow = tid >> 4, scol = (tid & 15) * 4;      // half0 stage: 512 thr, cols 0..511
    int tid2 = tid - 256;                             // half1 stage: warps 8-15
    int srow2 = tid2 >> 3, scol2 = (tid2 & 7) * 4;    // cols 512..1023
    int rm = tid >> 4, rn = (tid & 15) * 2;           // reduce: 2 outputs/thread
    int ar0 = lq * HS_STRIDE + lr;
    int kbase = kq * 128;

    for (int t = 0; t < T; t++) {
        int cur = t & 1, nxt = cur ^ 1;
        unsigned tgt = base + 1 + (unsigned)t;

        float2 xp = __ldcs((const float2*)(g_xproj + ((size_t)t * B + b0 + rm) * H + n0 + rn));

        // ---- poll A: warp 0 waits for producers 0..15 (h cols 0..511);
        //      all other warps sleep at the barrier (no memory traffic)
        if (wid == 0) {
            unsigned v;
            do { v = (lane < 16) ? ld_acq(gflag + lane) : tgt; }
            while (__any_sync(0xffffffffu, (int)(v - tgt) < 0));
        }
        __syncthreads();                               // S1: half0 ready

        // ---- stage half0 (cols 0..511), all 512 threads
        {
            const float* hg = g_h + cur * BH + (b0 + srow) * H + scol;
            float* hd = h_s + srow * HS_STRIDE + scol;
#pragma unroll
            for (int j = 0; j < 8; j++)
                *(float4*)(hd + j * 64) = __ldcg((const float4*)(hg + j * 64));
        }
        __syncthreads();                               // S2: half0 staged

        float acc[2][2][4];
#pragma unroll
        for (int mt = 0; mt < 2; mt++)
#pragma unroll
            for (int nt = 0; nt < 2; nt++)
#pragma unroll
                for (int c = 0; c < 4; c++) acc[mt][nt][c] = 0.f;

        if (kq < 4) {
            // mma over this warp's k-slice in half0
#pragma unroll
            for (int ks = 0; ks < 16; ks++) {
                int ka = kbase + ks * 8;
#pragma unroll
                for (int mt = 0; mt < 2; mt++) {
                    const float* ap = h_s + mt * 16 * HS_STRIDE + ar0 + ka;
                    unsigned a0 = f2u(ap[0]), a1 = f2u(ap[8 * HS_STRIDE]);
                    unsigned a2 = f2u(ap[4]), a3 = f2u(ap[8 * HS_STRIDE + 4]);
#pragma unroll
                    for (int nt = 0; nt < 2; nt++)
                        MMA(acc[mt][nt], a0, a1, a2, a3,
                            f2u(Br[nt][ks][0]), f2u(Br[nt][ks][1]));
                }
            }
        } else {
            // ---- poll B: warp 8 waits for producers 16..31 (h cols 512..1023);
            //      warps 9-15 sleep at the named barrier
            if (wid == 8) {
                unsigned v;
                do { v = (lane < 16) ? ld_acq(gflag + 16 + lane) : tgt; }
                while (__any_sync(0xffffffffu, (int)(v - tgt) < 0));
            }
            asm volatile("bar.sync 1, 256;" ::: "memory");   // half1 ready (warps 8-15)

            // stage half1 (cols 512..1023), warps 8-15
            {
                const float* hg2 = g_h + cur * BH + (b0 + srow2) * H + 512 + scol2;
                float* hd2 = h_s + srow2 * HS_STRIDE + 512 + scol2;
#pragma unroll
                for (int j = 0; j < 16; j++)
                    *(float4*)(hd2 + j * 32) = __ldcg((const float4*)(hg2 + j * 32));
            }
            asm volatile("bar.sync 1, 256;" ::: "memory");   // half1 staged

            // mma over this warp's k-slice in half1
#pragma unroll
            for (int ks = 0; ks < 16; ks++) {
                int ka = kbase + ks * 8;
#pragma unroll
                for (int mt = 0; mt < 2; mt++) {
                    const float* ap = h_s + mt * 16 * HS_STRIDE + ar0 + ka;
                    unsigned a0 = f2u(ap[0]), a1 = f2u(ap[8 * HS_STRIDE]);
                    unsigned a2 = f2u(ap[4]), a3 = f2u(ap[8 * HS_STRIDE + 4]);
#pragma unroll
                    for (int nt = 0; nt < 2; nt++)
                        MMA(acc[mt][nt], a0, a1, a2, a3,
                            f2u(Br[nt][ks][0]), f2u(Br[nt][ks][1]));
                }
            }
        }

        // write k-split partials (disjoint kq regions; ordered by S3)
        {
            float* pp = part + kq * (32 * P_STRIDE);
#pragma unroll
            for (int mt = 0; mt < 2; mt++)
#pragma unroll
                for (int nt = 0; nt < 2; nt++) {
                    int m = mt * 16 + lq, n = nh * 16 + nt * 8 + lr * 2;
                    pp[m * P_STRIDE + n]           = acc[mt][nt][0];
                    pp[m * P_STRIDE + n + 1]       = acc[mt][nt][1];
                    pp[(m + 8) * P_STRIDE + n]     = acc[mt][nt][2];
                    pp[(m + 8) * P_STRIDE + n + 1] = acc[mt][nt][3];
                }
        }
        __syncthreads();                               // S3: partials complete

        // packed reduce + fast tanh + store
        {
            float2 s = xp;
            const float* pb = part + rm * P_STRIDE + rn;
#pragma unroll
            for (int k = 0; k < 8; k++)
                addx2(s, *(const float2*)(pb + k * (32 * P_STRIDE)));
            float2 ov = make_float2(rtf(ftanh(s.x)), rtf(ftanh(s.y)));
            __stcg((float2*)(g_h + nxt * BH + (b0 + rm) * H + n0 + rn), ov);
        }

        __syncthreads();                               // S4: stores issued CTA-wide
        if (tid == 0) st_rel(&g_flags[blk], tgt + 1);
    }
}

// ---------------- Phase 3: y = h_final · W_ho^T + b_ho ----------------
__global__ __launch_bounds__(256) void out_k(const float* __restrict__ Who,
                                             const float* __restrict__ bho,
                                             float* __restrict__ y) {
    int idx = blockIdx.x * 256 + threadIdx.x;   // idx = b*512 + o
    int o = idx & (O - 1), bb = idx >> 9;
    const float4* hv = (const float4*)(g_h + bb * H);
    const float4* wv = (const float4*)(Who + (size_t)o * H);
    float s = 0.f;
#pragma unroll 8
    for (int j = 0; j < H / 4; j++) {
        float4 a = hv[j], w = wv[j];
        s += a.x * w.x + a.y * w.y + a.z * w.z + a.w * w.w;
    }
    y[idx] = s + bho[o];
}

extern "C" void kernel_launch(void* const* d_in, const int* in_sizes, int n_in,
                              void* d_out, int out_size) {
    const float* x   = (const float*)d_in[0];
    const float* Wih = (const float*)d_in[1];
    const float* bih = (const float*)d_in[2];
    const float* Who = (const float*)d_in[3];
    const float* bho = (const float*)d_in[4];

    cudaFuncSetAttribute(scan_k, cudaFuncAttributeMaxDynamicSharedMemorySize, SCAN_SMEM);

    xproj_k<<<dim3((B * T) / 64, H / 256), 256>>>(x, Wih, bih);
    scan_k<<<NCTA, 512, SCAN_SMEM>>>(Wih);
    out_k<<<(B * O) / 256, 256>>>(Who, bho, (float*)d_out);
}